// round 1
// baseline (speedup 1.0000x reference)
#include <cuda_runtime.h>

#define NUM_USERS 100000
#define NUM_ITEMS 50000
#define N_NODES   150000
#define C         64
#define NNZ       2400000
#define BATCH     8192
#define NEG_SLOPE 0.1f
#define EPS       1e-12f

// Scratch: ping-pong propagation buffers + accumulator (3 x 38.4 MB)
__device__ float g_bufA[(size_t)N_NODES * C];
__device__ float g_bufB[(size_t)N_NODES * C];
__device__ float g_acc [(size_t)N_NODES * C];

__device__ __forceinline__ float lrelu(float x) {
    return x >= 0.0f ? x : NEG_SLOPE * x;
}

__device__ __forceinline__ float warp_sum(float s) {
#pragma unroll
    for (int o = 16; o; o >>= 1) s += __shfl_xor_sync(0xffffffffu, s, o);
    return s;
}

// One warp per node row (64 floats = 32 lanes x float2).
// Normalizes the concatenated preference matrix into bufA and acc; zeroes bufB.
__global__ __launch_bounds__(256) void k_init(const float* __restrict__ up,
                                              const float* __restrict__ ip) {
    int row = blockIdx.x * (blockDim.x >> 5) + (threadIdx.x >> 5);
    if (row >= N_NODES) return;
    int lane = threadIdx.x & 31;

    const float* src = (row < NUM_USERS)
                           ? (up + (size_t)row * C)
                           : (ip + (size_t)(row - NUM_USERS) * C);
    float2 v = reinterpret_cast<const float2*>(src)[lane];
    v.x = lrelu(v.x);
    v.y = lrelu(v.y);
    float s = warp_sum(v.x * v.x + v.y * v.y);
    float inv = 1.0f / fmaxf(sqrtf(s), EPS);
    v.x *= inv; v.y *= inv;

    size_t idx = (size_t)row * 32 + lane;
    reinterpret_cast<float2*>(g_bufA)[idx] = v;
    reinterpret_cast<float2*>(g_acc)[idx]  = v;
    reinterpret_cast<float2*>(g_bufB)[idx] = make_float2(0.0f, 0.0f);
}

// SpMM scatter: 16 threads per edge, float4 each.
// flip==0: read bufA, accumulate into bufB.  flip==1: read bufB -> bufA.
__global__ __launch_bounds__(256) void k_spmm(const int* __restrict__ erow,
                                              const int* __restrict__ ecol,
                                              const float* __restrict__ eval,
                                              int flip) {
    const float* __restrict__ p  = flip ? g_bufB : g_bufA;
    float* __restrict__       pn = flip ? g_bufA : g_bufB;

    int tid = blockIdx.x * blockDim.x + threadIdx.x;
    int e = tid >> 4;
    int q = tid & 15;
    if (e >= NNZ) return;

    int   r = erow[e];
    int   c = ecol[e];
    float v = eval[e];

    float4 x = __ldg(reinterpret_cast<const float4*>(p + (size_t)c * C) + q);
    x.x *= v; x.y *= v; x.z *= v; x.w *= v;

    float* dst = pn + (size_t)r * C + q * 4;
    asm volatile("red.global.add.v4.f32 [%0], {%1,%2,%3,%4};"
                 :: "l"(dst), "f"(x.x), "f"(x.y), "f"(x.z), "f"(x.w)
                 : "memory");
}

// Normalize the freshly scattered buffer in place, acc += normalized,
// and zero the other buffer (next scatter target). One warp per row.
__global__ __launch_bounds__(256) void k_norm(int flip) {
    float* __restrict__ pn   = flip ? g_bufA : g_bufB;  // just written by spmm
    float* __restrict__ pold = flip ? g_bufB : g_bufA;  // becomes next target

    int row = blockIdx.x * (blockDim.x >> 5) + (threadIdx.x >> 5);
    if (row >= N_NODES) return;
    int lane = threadIdx.x & 31;
    size_t idx = (size_t)row * 32 + lane;

    float2 v = reinterpret_cast<float2*>(pn)[idx];
    v.x = lrelu(v.x);
    v.y = lrelu(v.y);
    float s = warp_sum(v.x * v.x + v.y * v.y);
    float inv = 1.0f / fmaxf(sqrtf(s), EPS);
    v.x *= inv; v.y *= inv;

    reinterpret_cast<float2*>(pn)[idx] = v;
    float2 a = reinterpret_cast<float2*>(g_acc)[idx];
    a.x += v.x; a.y += v.y;
    reinterpret_cast<float2*>(g_acc)[idx] = a;
    reinterpret_cast<float2*>(pold)[idx] = make_float2(0.0f, 0.0f);
}

// Scoring: one warp per batch element; 3 dot products of length 64.
// merged = acc/4  ->  dot(merged_u, merged_i) = dot(acc_u, acc_i) / 16.
__global__ __launch_bounds__(256) void k_score(const int* __restrict__ users,
                                               const int* __restrict__ adj,
                                               const int* __restrict__ weak,
                                               const int* __restrict__ strong,
                                               float* __restrict__ out) {
    int b = blockIdx.x * (blockDim.x >> 5) + (threadIdx.x >> 5);
    if (b >= BATCH) return;
    int lane = threadIdx.x & 31;

    const float2* acc2 = reinterpret_cast<const float2*>(g_acc);
    int u  = users[b];
    int i0 = NUM_USERS + adj[b];
    int i1 = NUM_USERS + weak[b];
    int i2 = NUM_USERS + strong[b];

    float2 uv = acc2[(size_t)u  * 32 + lane];
    float2 a0 = acc2[(size_t)i0 * 32 + lane];
    float2 a1 = acc2[(size_t)i1 * 32 + lane];
    float2 a2 = acc2[(size_t)i2 * 32 + lane];

    float d0 = warp_sum(uv.x * a0.x + uv.y * a0.y);
    float d1 = warp_sum(uv.x * a1.x + uv.y * a1.y);
    float d2 = warp_sum(uv.x * a2.x + uv.y * a2.y);

    if (lane == 0) {
        out[0 * BATCH + b] = 1.0f / (1.0f + expf(-d0 * (1.0f / 16.0f)));
        out[1 * BATCH + b] = 1.0f / (1.0f + expf(-d1 * (1.0f / 16.0f)));
        out[2 * BATCH + b] = 1.0f / (1.0f + expf(-d2 * (1.0f / 16.0f)));
    }
}

extern "C" void kernel_launch(void* const* d_in, const int* in_sizes, int n_in,
                              void* d_out, int out_size) {
    const int*   users  = (const int*)d_in[0];
    const int*   adj    = (const int*)d_in[1];
    const int*   weak   = (const int*)d_in[2];
    const int*   strong = (const int*)d_in[3];
    const int*   erow   = (const int*)d_in[4];
    const int*   ecol   = (const int*)d_in[5];
    const float* eval   = (const float*)d_in[6];
    const float* up     = (const float*)d_in[7];
    const float* ip     = (const float*)d_in[8];
    float* out = (float*)d_out;

    const int ROWS_BLOCKS = (N_NODES + 7) / 8;            // 8 warps/block
    const int SPMM_BLOCKS = (NNZ * 16 + 255) / 256;

    k_init<<<ROWS_BLOCKS, 256>>>(up, ip);

    int flip = 0;
    for (int layer = 0; layer < 3; ++layer) {
        k_spmm<<<SPMM_BLOCKS, 256>>>(erow, ecol, eval, flip);
        k_norm<<<ROWS_BLOCKS, 256>>>(flip);
        flip ^= 1;
    }

    k_score<<<(BATCH + 7) / 8, 256>>>(users, adj, weak, strong, out);
}